// round 5
// baseline (speedup 1.0000x reference)
#include <cuda_runtime.h>
#include <cuda_bf16.h>
#include <mma.h>
#include <cstdint>

using namespace nvcuda;

// Fixed shapes
#define B_      2
#define L_      512
#define D_      256
#define TILE    64
#define THREADS 256
#define SST     264                      // 256 + 8 pad (528B rows, 16B-multiple)
#define TILE_ELEMS (TILE * SST)          // 16896 bf16
#define SMEM_BYTES (4 * TILE_ELEMS * 2)  // 135168 B

// Split-bf16 scratch (prep output), row-major [B_*L_][D_]
__device__ __nv_bfloat16 gAhi[B_*L_*D_];  // bf16(x*w1)
__device__ __nv_bfloat16 gAlo[B_*L_*D_];  // residual
__device__ __nv_bfloat16 gBhi[B_*L_*D_];  // bf16(x)
__device__ __nv_bfloat16 gBlo[B_*L_*D_];  // residual

// out[b,i,j] = sum_d x[b,i,d]*w1[d]*x[b,j,d] + bias
// (lin_i - lin_j cancels under (P+P^T)/2; w2 dead.)
// a*x ≈ ahi*xhi + ahi*xlo + alo*xhi (rel ~2^-18)

// ============================ prep ============================
__global__ void prep_kernel(const float* __restrict__ x, const float* __restrict__ W) {
    int idx = blockIdx.x * blockDim.x + threadIdx.x;   // over B*L*64 float4
    int c4  = idx & 63;
    float4 xv = ((const float4*)x)[idx];
    float4 wv = ((const float4*)W)[c4];
    float xa[4] = {xv.x, xv.y, xv.z, xv.w};
    float wa[4] = {wv.x, wv.y, wv.z, wv.w};
    __nv_bfloat16 ah[4], al[4], bh[4], bl[4];
    #pragma unroll
    for (int j = 0; j < 4; j++) {
        float a = xa[j] * wa[j];
        ah[j] = __float2bfloat16(a);
        al[j] = __float2bfloat16(a - __bfloat162float(ah[j]));
        bh[j] = __float2bfloat16(xa[j]);
        bl[j] = __float2bfloat16(xa[j] - __bfloat162float(bh[j]));
    }
    ((uint2*)gAhi)[idx] = *(uint2*)ah;
    ((uint2*)gAlo)[idx] = *(uint2*)al;
    ((uint2*)gBhi)[idx] = *(uint2*)bh;
    ((uint2*)gBlo)[idx] = *(uint2*)bl;
}

// ============================ GEMM ============================
__device__ __forceinline__ uint32_t smem_u32(const void* p) {
    uint32_t a;
    asm("{ .reg .u64 t; cvta.to.shared.u64 t, %1; cvt.u32.u64 %0, t; }" : "=r"(a) : "l"(p));
    return a;
}
__device__ __forceinline__ void cp_async16(uint32_t dst, const void* src) {
    asm volatile("cp.async.cg.shared.global [%0], [%1], 16;" :: "r"(dst), "l"(src));
}

__global__ __launch_bounds__(THREADS, 1)
void gemm_kernel(const float* __restrict__ bias_p, float* __restrict__ out) {
    extern __shared__ __align__(16) __nv_bfloat16 smem[];
    __nv_bfloat16* sAhi = smem;
    __nv_bfloat16* sAlo = smem + TILE_ELEMS;
    __nv_bfloat16* sBhi = smem + 2 * TILE_ELEMS;
    __nv_bfloat16* sBlo = smem + 3 * TILE_ELEMS;

    const int bz  = blockIdx.z;
    const int ti  = blockIdx.y;
    const int tj  = blockIdx.x;
    const int tid = threadIdx.x;
    const int warp = tid >> 5;
    const int wr = warp >> 2;     // 0..1 (32-row band)
    const int wc = warp & 3;      // 0..3 (16-col band)

    const uint32_t sbase = smem_u32(smem);
    const size_t offA = (size_t)(bz * L_ + ti * TILE) * D_;
    const size_t offB = (size_t)(bz * L_ + tj * TILE) * D_;

    // ---- async copy 4 matrices: per thread 8 x 16B per matrix ----
    const __nv_bfloat16* srcs[4] = {gAhi + offA, gAlo + offA, gBhi + offB, gBlo + offB};
    #pragma unroll
    for (int m = 0; m < 4; m++) {
        const uint4* src = (const uint4*)srcs[m];
        uint32_t dbase = sbase + (uint32_t)(m * TILE_ELEMS) * 2;
        #pragma unroll
        for (int i = 0; i < 8; i++) {
            int lin = i * THREADS + tid;
            int row = lin >> 5;          // 0..63
            int c   = lin & 31;          // 16B chunk within row
            cp_async16(dbase + (uint32_t)(row * SST + c * 8) * 2, src + row * 32 + c);
        }
    }
    asm volatile("cp.async.commit_group;" ::: "memory");
    asm volatile("cp.async.wait_group 0;" ::: "memory");
    __syncthreads();

    // ---- 48 uninterrupted wmma k-steps ----
    wmma::fragment<wmma::accumulator, 16, 16, 16, float> acc[2];
    wmma::fill_fragment(acc[0], 0.0f);
    wmma::fill_fragment(acc[1], 0.0f);

    const __nv_bfloat16* pa[3] = {sAhi, sAhi, sAlo};
    const __nv_bfloat16* pb[3] = {sBhi, sBlo, sBhi};

    #pragma unroll
    for (int p = 0; p < 3; p++) {
        const __nv_bfloat16* Abase = pa[p] + (wr * 32) * SST;
        const __nv_bfloat16* Bbase = pb[p] + (wc * 16) * SST;
        #pragma unroll
        for (int kk = 0; kk < D_; kk += 16) {
            wmma::fragment<wmma::matrix_a, 16, 16, 16, __nv_bfloat16, wmma::row_major> af0, af1;
            wmma::fragment<wmma::matrix_b, 16, 16, 16, __nv_bfloat16, wmma::col_major> bf;
            wmma::load_matrix_sync(af0, Abase + kk, SST);
            wmma::load_matrix_sync(af1, Abase + 16 * SST + kk, SST);
            wmma::load_matrix_sync(bf,  Bbase + kk, SST);
            wmma::mma_sync(acc[0], af0, bf, acc[0]);
            wmma::mma_sync(acc[1], af1, bf, acc[1]);
        }
    }

    // ---- epilogue ----
    const float bias = bias_p[0];
    #pragma unroll
    for (int r = 0; r < 2; r++) {
        #pragma unroll
        for (int t = 0; t < acc[r].num_elements; t++)
            acc[r].x[t] += bias;
        int gi = ti * TILE + wr * 32 + r * 16;
        int gj = tj * TILE + wc * 16;
        float* dst = out + (size_t)bz * L_ * L_ + (size_t)gi * L_ + gj;
        wmma::store_matrix_sync(dst, acc[r], L_, wmma::mem_row_major);
    }
}

// ---------------------------------------------------------------------------
// d_in[0] = inputs f32 (2,512,256), d_in[1] = W f32 (512,1), d_in[2] = b f32 (1,)
// d_out   = f32 (2,512,512,1)
// ---------------------------------------------------------------------------
extern "C" void kernel_launch(void* const* d_in, const int* in_sizes, int n_in,
                              void* d_out, int out_size) {
    const float* x    = (const float*)d_in[0];
    const float* W    = (const float*)d_in[1];
    const float* bptr = (const float*)d_in[2];
    float* out = (float*)d_out;

    static bool attr_set = false;
    if (!attr_set) {
        cudaFuncSetAttribute(gemm_kernel,
                             cudaFuncAttributeMaxDynamicSharedMemorySize, SMEM_BYTES);
        attr_set = true;
    }

    prep_kernel<<<(B_ * L_ * D_ / 4) / 256, 256>>>(x, W);

    dim3 grid(L_ / TILE, L_ / TILE, B_);   // (8, 8, 2)
    gemm_kernel<<<grid, THREADS, SMEM_BYTES>>>(bptr, out);
}